// round 6
// baseline (speedup 1.0000x reference)
#include <cuda_runtime.h>

typedef unsigned long long u64;

#define LOG2E 1.4426950408889634f
#define LN2   0.6931471805599453f
#define B    512
#define TT   1024
#define L    48
#define RING 16   // cp.async emission ring slots (192B each)

__device__ float g_fwd[B];
__device__ float g_gold[B];

static __device__ __forceinline__ u64 pk2(float lo, float hi){ u64 r; asm("mov.b64 %0, {%1, %2};" : "=l"(r) : "f"(lo), "f"(hi)); return r; }
static __device__ __forceinline__ void upk2(u64 v, float& lo, float& hi){ asm("mov.b64 {%0, %1}, %2;" : "=f"(lo), "=f"(hi) : "l"(v)); }
static __device__ __forceinline__ u64 fma2(u64 a, u64 b, u64 c){ u64 d; asm("fma.rn.f32x2 %0, %1, %2, %3;" : "=l"(d) : "l"(a), "l"(b), "l"(c)); return d; }
static __device__ __forceinline__ u64 mul2(u64 a, u64 b){ u64 d; asm("mul.rn.f32x2 %0, %1, %2;" : "=l"(d) : "l"(a), "l"(b)); return d; }
static __device__ __forceinline__ u64 add2(u64 a, u64 b){ u64 d; asm("add.rn.f32x2 %0, %1, %2;" : "=l"(d) : "l"(a), "l"(b)); return d; }
static __device__ __forceinline__ float ex2f(float x){ float y; asm("ex2.approx.ftz.f32 %0, %1;" : "=f"(y) : "f"(x)); return y; }
static __device__ __forceinline__ float lg2f(float x){ float y; asm("lg2.approx.ftz.f32 %0, %1;" : "=f"(y) : "f"(x)); return y; }
static __device__ __forceinline__ unsigned smem_u32(const void* p){
    unsigned a; asm("{ .reg .u64 t; cvta.to.shared.u64 t, %1; cvt.u32.u64 %0, t; }" : "=r"(a) : "l"(p)); return a; }

// ---------------------------------------------------------------------------
// Forward kernel: 512 blocks x 32 threads — ONE warp per sequence, no block
// barriers. Lane i (i<24) owns labels (2i, 2i+1) packed in f32x2. State is
// exchanged via a duplicated smem layout (u_k,u_k,u_{k+1},u_{k+1}) written
// with one STS.128/lane so consumer LDS.128 yields splatted FMA2 operands.
// Emissions stream through a 16-slot cp.async ring (15-step lookahead).
// Mask is 1 bit/step (uniform per sequence). Renorm: exact pow-2, every 4.
// ---------------------------------------------------------------------------
__global__ __launch_bounds__(32) void crf_fwd_kernel(
    const float* __restrict__ em, const int* __restrict__ mask,
    const float* __restrict__ trans, const float* __restrict__ startt,
    const float* __restrict__ endt)
{
    __shared__ __align__(16) float udup[2][128];      // dup state ping-pong
    __shared__ __align__(16) float ring[RING * 48];   // emission ring (3KB)
    __shared__ unsigned mb[32];                       // mask bits (1024 steps)

    const int lane = threadIdx.x;
    const int i  = lane < 24 ? lane : 23;             // clamp shadow lanes
    const int b  = blockIdx.x;
    const int j0 = 2 * i, j1 = 2 * i + 1;

    // ---- mask bits via ballot (prologue) ----
    #pragma unroll 1
    for (int k = 0; k < 32; k++) {
        int v = mask[b * TT + k * 32 + lane];
        unsigned w = __ballot_sync(0xFFFFFFFFu, v != 0);
        if (lane == k) mb[k] = w;
    }

    // ---- transition columns (j0, j1), exponentiated, packed ----
    u64 et[L];
    #pragma unroll
    for (int k = 0; k < L; k++) {
        float e0 = ex2f(trans[k * L + j0] * LOG2E);
        float e1 = ex2f(trans[k * L + j1] * LOG2E);
        et[k] = pk2(e0, e1);
    }
    const float eEnd0 = ex2f(endt[j0] * LOG2E);
    const float eEnd1 = ex2f(endt[j1] * LOG2E);

    // ---- initial state u0 = exp(start + em[0]) ----
    u64 res;
    {
        float a = ex2f((startt[j0] + em[(size_t)b * TT * L + j0]) * LOG2E);
        float c = ex2f((startt[j1] + em[(size_t)b * TT * L + j1]) * LOG2E);
        res = pk2(a, c);
        float lo, hi; upk2(res, lo, hi);
        reinterpret_cast<float4*>(&udup[0][0])[lane] = make_float4(lo, lo, hi, hi);
    }

    // ---- cp.async ring prologue: lanes 0..11 copy 16B each (48 floats/row) ----
    const float* gsrc = em + (size_t)b * TT * L + lane * 4;
    const unsigned ring_base = smem_u32(&ring[0]);
    const unsigned dst_off = (unsigned)(lane * 16);
    for (int tp = 1; tp < RING; ++tp) {
        if (lane < 12) {
            const float* src = gsrc + (size_t)tp * L;
            unsigned d = ring_base + (unsigned)tp * 192u + dst_off;
            asm volatile("cp.async.cg.shared.global [%0], [%1], 16;" :: "r"(d), "l"(src));
        }
        asm volatile("cp.async.commit_group;");
    }
    asm volatile("cp.async.wait_group 14;");
    __syncwarp();

    int iA = 0;   // exact integer log2 credit
    const ulonglong2* rd = reinterpret_cast<const ulonglong2*>(&udup[0][0]);
    float4*           wr = reinterpret_cast<float4*>(&udup[1][0]);

    #pragma unroll 1
    for (int t = 1; t < TT; ++t) {
        // ---- 48x48 matvec: 24 broadcast LDS.128, 48 FMA2 into 4 accums ----
        u64 a0 = 0, a1 = 0, a2 = 0, a3 = 0;
        u64 first = 0;
        #pragma unroll
        for (int q = 0; q < 12; q++) {
            ulonglong2 wA = rd[2 * q];        // (splat u_{4q},   splat u_{4q+1})
            ulonglong2 wB = rd[2 * q + 1];    // (splat u_{4q+2}, splat u_{4q+3})
            if (q == 0) first = wA.x;
            a0 = fma2(wA.x, et[4 * q + 0], a0);
            a1 = fma2(wA.y, et[4 * q + 1], a1);
            a2 = fma2(wB.x, et[4 * q + 2], a2);
            a3 = fma2(wB.y, et[4 * q + 3], a3);
        }
        u64 dot = add2(add2(a0, a1), add2(a2, a3));

        // ---- emissions from ring + uniform mask bit ----
        const int slot = t & (RING - 1);
        u64 emp = *reinterpret_cast<const u64*>(&ring[slot * 48 + j0]);
        float emLo, emHi; upk2(emp, emLo, emHi);
        u64 Ee   = pk2(ex2f(emLo * LOG2E), ex2f(emHi * LOG2E));
        u64 prod = mul2(dot, Ee);
        bool mbit = (mb[t >> 5] >> (t & 31)) & 1u;
        u64 sel = mbit ? prod : res;

        if ((t & 3) == 0) {                   // exact power-of-2 renorm (from u[0])
            unsigned eb = (unsigned)first & 0x7F800000u;
            float f = __uint_as_float(0x7F000000u - eb);
            sel = mul2(sel, pk2(f, f));
            iA += (int)(eb >> 23) - 127;
        }
        res = sel;

        // ---- publish new state (dup layout, one STS.128) ----
        float lo, hi; upk2(res, lo, hi);
        wr[lane] = make_float4(lo, lo, hi, hi);

        // ---- refill ring slot for row t+15 (clamped) ----
        {
            int tf = t + (RING - 1); if (tf > TT - 1) tf = TT - 1;
            if (lane < 12) {
                const float* src = gsrc + (size_t)tf * L;
                unsigned d = ring_base + (unsigned)(tf & (RING - 1)) * 192u + dst_off;
                asm volatile("cp.async.cg.shared.global [%0], [%1], 16;" :: "r"(d), "l"(src));
            }
            asm volatile("cp.async.commit_group;");
            asm volatile("cp.async.wait_group 14;");
        }

        // swap ping-pong
        float4* nw = (float4*)rd;
        rd = (const ulonglong2*)wr;
        wr = nw;

        __syncwarp();
    }

    // ---- finalize: logZ = (log2(sum_j u_j * expEnd_j) + credit) * ln2 ----
    float lo, hi; upk2(res, lo, hi);
    float s = (lane < 24) ? (lo * eEnd0 + hi * eEnd1) : 0.f;
    #pragma unroll
    for (int o = 16; o > 0; o >>= 1) s += __shfl_down_sync(0xFFFFFFFFu, s, o);
    if (lane == 0) g_fwd[b] = (lg2f(s) + (float)iA) * LN2;
}

// ---------------------------------------------------------------------------
// Gold score kernel: one block per batch element.
// ---------------------------------------------------------------------------
__global__ __launch_bounds__(256, 4) void crf_gold_kernel(
    const float* __restrict__ em, const int* __restrict__ labels,
    const int* __restrict__ mask, const float* __restrict__ trans,
    const float* __restrict__ startt, const float* __restrict__ endt)
{
    __shared__ float red[256];
    __shared__ int   redc[256];
    const int b = blockIdx.x;
    const int tid = threadIdx.x;

    float acc = 0.f;
    int cnt = 0;
    for (int t = tid; t < TT; t += 256) {
        int l = labels[b * TT + t];
        int m = mask[b * TT + t];
        cnt += m;
        float e = em[((size_t)(b * TT) + t) * L + l];
        if (t == 0) {
            acc += startt[l] + e;
        } else {
            int lp = labels[b * TT + t - 1];
            acc += (e + trans[l * L + lp]) * (float)m;
        }
    }
    red[tid] = acc; redc[tid] = cnt;
    __syncthreads();
    for (int s = 128; s > 0; s >>= 1) {
        if (tid < s) { red[tid] += red[tid + s]; redc[tid] += redc[tid + s]; }
        __syncthreads();
    }
    if (tid == 0) {
        int len = redc[0] - 1;
        int last = labels[b * TT + len];
        g_gold[b] = red[0] + endt[last];
    }
}

// ---------------------------------------------------------------------------
// Final reduction: mean(fwd - gold)
// ---------------------------------------------------------------------------
__global__ __launch_bounds__(512, 1) void crf_final_kernel(float* __restrict__ out)
{
    __shared__ float red[512];
    int tid = threadIdx.x;
    red[tid] = g_fwd[tid] - g_gold[tid];
    __syncthreads();
    for (int s = 256; s > 0; s >>= 1) {
        if (tid < s) red[tid] += red[tid + s];
        __syncthreads();
    }
    if (tid == 0) out[0] = red[0] * (1.0f / (float)B);
}

extern "C" void kernel_launch(void* const* d_in, const int* in_sizes, int n_in,
                              void* d_out, int out_size)
{
    const float* em     = (const float*)d_in[0];
    const int*   labels = (const int*)  d_in[1];
    const int*   mask   = (const int*)  d_in[2];
    const float* trans  = (const float*)d_in[3];
    const float* startt = (const float*)d_in[4];
    const float* endt   = (const float*)d_in[5];
    float* out = (float*)d_out;

    crf_fwd_kernel<<<B, 32>>>(em, mask, trans, startt, endt);
    crf_gold_kernel<<<B, 256>>>(em, labels, mask, trans, startt, endt);
    crf_final_kernel<<<1, 512>>>(out);
}

// round 7
// speedup vs baseline: 1.7610x; 1.7610x over previous
#include <cuda_runtime.h>

typedef unsigned long long u64;

#define LOG2E 1.4426950408889634f
#define LN2   0.6931471805599453f
#define B    512
#define TT   1024
#define L    48
#define RING 16   // cp.async emission ring slots (512B each)

__device__ float g_fwd[B];
__device__ float g_gold[B];

static __device__ __forceinline__ u64 pk2(float lo, float hi){ u64 r; asm("mov.b64 %0, {%1, %2};" : "=l"(r) : "f"(lo), "f"(hi)); return r; }
static __device__ __forceinline__ u64 fma2(u64 a, u64 b, u64 c){ u64 d; asm("fma.rn.f32x2 %0, %1, %2, %3;" : "=l"(d) : "l"(a), "l"(b), "l"(c)); return d; }
static __device__ __forceinline__ u64 mul2(u64 a, u64 b){ u64 d; asm("mul.rn.f32x2 %0, %1, %2;" : "=l"(d) : "l"(a), "l"(b)); return d; }
static __device__ __forceinline__ u64 add2(u64 a, u64 b){ u64 d; asm("add.rn.f32x2 %0, %1, %2;" : "=l"(d) : "l"(a), "l"(b)); return d; }
static __device__ __forceinline__ float ex2f(float x){ float y; asm("ex2.approx.ftz.f32 %0, %1;" : "=f"(y) : "f"(x)); return y; }
static __device__ __forceinline__ float lg2f(float x){ float y; asm("lg2.approx.ftz.f32 %0, %1;" : "=f"(y) : "f"(x)); return y; }
static __device__ __forceinline__ unsigned smem_u32(const void* p){
    unsigned a; asm("{ .reg .u64 t; cvta.to.shared.u64 t, %1; cvt.u32.u64 %0, t; }" : "=r"(a) : "l"(p)); return a; }

// ---------------------------------------------------------------------------
// Forward kernel: 256 blocks x 64 threads, 2 sequences per block packed into
// f32x2 lanes. Thread j owns label j (j>=48 shadow label 47, results unread).
// Emissions stream through a 16-slot smem ring filled by cp.async (LDGSTS):
// completion via commit_group/wait_group(14) => 15-step (~2000cyc) lookahead.
// __launch_bounds__(64, 1): register ceiling 255 so et[48] (96 regs) stays
// register-resident — R5/R6 spilled it to local (regs=78/126, L1 45%+).
// Renorm every 4 steps by exact power-of-2 from exponent(u[0]).
// ---------------------------------------------------------------------------
__global__ __launch_bounds__(64, 1) void crf_fwd_kernel(
    const float* __restrict__ em, const int* __restrict__ mask,
    const float* __restrict__ trans, const float* __restrict__ startt,
    const float* __restrict__ endt)
{
    __shared__ __align__(16) u64   sh_u[2][64];        // ping-pong state
    __shared__ __align__(16) float sh_em[RING][128];   // ring: [0..47]=A, [64..111]=B
    __shared__ __align__(16) u64   sh_mm[TT];          // packed select masks (8KB)

    const int j  = threadIdx.x;
    const int jc = j < L ? j : (L - 1);                // clamp for shadow threads
    const int bA = blockIdx.x * 2, bB = bA + 1;

    // ---- pre-pack masks (once) ----
    for (int t = j; t < TT; t += 64) {
        unsigned a = mask[bA * TT + t] ? 0xFFFFFFFFu : 0u;
        unsigned b = mask[bB * TT + t] ? 0xFFFFFFFFu : 0u;
        sh_mm[t] = (u64)a | ((u64)b << 32);
    }

    // ---- transition column j, exponentiated, splatted ----
    u64 et[L];
    #pragma unroll
    for (int i = 0; i < L; i++) {
        float e = ex2f(trans[i * L + jc] * LOG2E);
        et[i] = pk2(e, e);
    }
    const float expEnd = ex2f(endt[jc] * LOG2E);

    // ---- initial state ----
    u64 res;
    {
        float sv = startt[jc];
        float a = ex2f((sv + em[(size_t)bA * TT * L + jc]) * LOG2E);
        float b = ex2f((sv + em[(size_t)bB * TT * L + jc]) * LOG2E);
        res = pk2(a, b);
        sh_u[0][j] = res;
    }

    // ---- cp.async producer setup: lanes 0..11 -> seq A, 12..23 -> seq B ----
    const float* gbase = (j < 12) ? (em + (size_t)bA * TT * L + j * 4)
                                  : (em + (size_t)bB * TT * L + (j - 12) * 4);
    const unsigned dst_off  = (j < 12) ? (unsigned)(j * 16) : (unsigned)(256 + (j - 12) * 16);
    const unsigned ring_base = smem_u32(&sh_em[0][0]);

    // prologue: fill slots 1..15 (one commit group per slot/row)
    for (int tp = 1; tp < RING; ++tp) {
        if (j < 24) {
            const float* src = gbase + (size_t)tp * L;
            unsigned d = ring_base + (unsigned)tp * 512u + dst_off;
            asm volatile("cp.async.cg.shared.global [%0], [%1], 16;" :: "r"(d), "l"(src));
        }
        asm volatile("cp.async.commit_group;");
    }
    asm volatile("cp.async.wait_group 14;");   // row 1 resident
    __syncthreads();

    int iAlo = 0, iAhi = 0;                    // exact integer log2 credits
    const u64* pr = sh_u[0];
    u64*       pw = sh_u[1];

    #pragma unroll 1
    for (int t = 1; t < TT; ++t) {
        // ---- 48x48 matvec (broadcast LDS of u, FMA2 into 4 accumulators) ----
        const ulonglong2* up = reinterpret_cast<const ulonglong2*>(pr);
        u64 a0 = 0, a1 = 0, a2 = 0, a3 = 0;
        u64 first = 0;
        #pragma unroll
        for (int q = 0; q < 12; q++) {
            ulonglong2 w0 = up[2 * q];
            ulonglong2 w1 = up[2 * q + 1];
            if (q == 0) first = w0.x;          // u[t-1][0] pair (renorm reference)
            a0 = fma2(w0.x, et[4 * q + 0], a0);
            a1 = fma2(w0.y, et[4 * q + 1], a1);
            a2 = fma2(w1.x, et[4 * q + 2], a2);
            a3 = fma2(w1.y, et[4 * q + 3], a3);
        }
        u64 dot = add2(add2(a0, a1), add2(a2, a3));

        // ---- emissions from ring + mask select ----
        const int slot = t & (RING - 1);
        float emA = sh_em[slot][jc];
        float emB = sh_em[slot][64 + jc];
        u64 Ee   = pk2(ex2f(emA * LOG2E), ex2f(emB * LOG2E));
        u64 prod = mul2(dot, Ee);
        u64 mm   = sh_mm[t];
        u64 sel  = (prod & mm) | (res & ~mm);

        if ((t & 3) == 0) {                    // exact power-of-2 renorm
            unsigned bLo = (unsigned)first, bHi = (unsigned)(first >> 32);
            unsigned eL = bLo & 0x7F800000u, eH = bHi & 0x7F800000u;
            sel = mul2(sel, pk2(__uint_as_float(0x7F000000u - eL),
                                __uint_as_float(0x7F000000u - eH)));
            iAlo += (int)(eL >> 23) - 127;
            iAhi += (int)(eH >> 23) - 127;
        }
        res = sel;
        pw[j] = res;

        // ---- refill ring slot for row t+15 (clamped; redundant dup is benign) ----
        {
            int tf = t + (RING - 1); if (tf > TT - 1) tf = TT - 1;
            if (j < 24) {
                const float* src = gbase + (size_t)tf * L;
                unsigned d = ring_base + (unsigned)(tf & (RING - 1)) * 512u + dst_off;
                asm volatile("cp.async.cg.shared.global [%0], [%1], 16;" :: "r"(d), "l"(src));
            }
            asm volatile("cp.async.commit_group;");
            asm volatile("cp.async.wait_group 14;");   // row t+1 resident
        }

        const u64* tmp = pr; pr = pw; pw = (u64*)tmp;
        __syncthreads();
    }

    // ---- finalize: logZ = (log2(sum_j u_j * exp(end_j)) + credit) * ln2 ----
    __syncthreads();
    sh_u[1][j] = mul2(res, pk2(expEnd, expEnd));       // res corresponds to pr buffer
    __syncthreads();
    if (j < 2) {
        const float* base = ((const float*)&sh_u[1][0]) + j;   // j=0: seqA, j=1: seqB
        float s = 0.f;
        #pragma unroll
        for (int q = 0; q < L; q++) s += base[2 * q];
        int credit = j ? iAhi : iAlo;
        g_fwd[bA + j] = (lg2f(s) + (float)credit) * LN2;
    }
}

// ---------------------------------------------------------------------------
// Gold score kernel: one block per batch element.
// ---------------------------------------------------------------------------
__global__ __launch_bounds__(256, 4) void crf_gold_kernel(
    const float* __restrict__ em, const int* __restrict__ labels,
    const int* __restrict__ mask, const float* __restrict__ trans,
    const float* __restrict__ startt, const float* __restrict__ endt)
{
    __shared__ float red[256];
    __shared__ int   redc[256];
    const int b = blockIdx.x;
    const int tid = threadIdx.x;

    float acc = 0.f;
    int cnt = 0;
    for (int t = tid; t < TT; t += 256) {
        int l = labels[b * TT + t];
        int m = mask[b * TT + t];
        cnt += m;
        float e = em[((size_t)(b * TT) + t) * L + l];
        if (t == 0) {
            acc += startt[l] + e;
        } else {
            int lp = labels[b * TT + t - 1];
            acc += (e + trans[l * L + lp]) * (float)m;
        }
    }
    red[tid] = acc; redc[tid] = cnt;
    __syncthreads();
    for (int s = 128; s > 0; s >>= 1) {
        if (tid < s) { red[tid] += red[tid + s]; redc[tid] += redc[tid + s]; }
        __syncthreads();
    }
    if (tid == 0) {
        int len = redc[0] - 1;
        int last = labels[b * TT + len];
        g_gold[b] = red[0] + endt[last];
    }
}

// ---------------------------------------------------------------------------
// Final reduction: mean(fwd - gold)
// ---------------------------------------------------------------------------
__global__ __launch_bounds__(512, 1) void crf_final_kernel(float* __restrict__ out)
{
    __shared__ float red[512];
    int tid = threadIdx.x;
    red[tid] = g_fwd[tid] - g_gold[tid];
    __syncthreads();
    for (int s = 256; s > 0; s >>= 1) {
        if (tid < s) red[tid] += red[tid + s];
        __syncthreads();
    }
    if (tid == 0) out[0] = red[0] * (1.0f / (float)B);
}

extern "C" void kernel_launch(void* const* d_in, const int* in_sizes, int n_in,
                              void* d_out, int out_size)
{
    const float* em     = (const float*)d_in[0];
    const int*   labels = (const int*)  d_in[1];
    const int*   mask   = (const int*)  d_in[2];
    const float* trans  = (const float*)d_in[3];
    const float* startt = (const float*)d_in[4];
    const float* endt   = (const float*)d_in[5];
    float* out = (float*)d_out;

    crf_fwd_kernel<<<B / 2, 64>>>(em, mask, trans, startt, endt);
    crf_gold_kernel<<<B, 256>>>(em, labels, mask, trans, startt, endt);
    crf_final_kernel<<<1, 512>>>(out);
}

// round 8
// speedup vs baseline: 1.7826x; 1.0123x over previous
#include <cuda_runtime.h>

typedef unsigned long long u64;

#define LOG2E 1.4426950408889634f
#define LN2   0.6931471805599453f
#define B    512
#define TT   1024
#define L    48
#define RING 16   // cp.async emission ring slots (512B each)

__device__ float g_fwd[B];
__device__ float g_gold[B];

static __device__ __forceinline__ float ex2f(float x){ float y; asm("ex2.approx.ftz.f32 %0, %1;" : "=f"(y) : "f"(x)); return y; }
static __device__ __forceinline__ float lg2f(float x){ float y; asm("lg2.approx.ftz.f32 %0, %1;" : "=f"(y) : "f"(x)); return y; }
static __device__ __forceinline__ unsigned smem_u32(const void* p){
    unsigned a; asm("{ .reg .u64 t; cvta.to.shared.u64 t, %1; cvt.u32.u64 %0, t; }" : "=r"(a) : "l"(p)); return a; }

// ---------------------------------------------------------------------------
// Forward kernel: 256 blocks x 96 threads (3 warps), 2 sequences per block,
// UNPACKED: thread (seq = tid/48, j = tid%48) runs a scalar 48-FMA dot for
// label j of its sequence. et[48] scalar floats = 48 regs -> no spills
// (R5-R7 spilled the duplicated f32x2 et[48] = 96 regs; L1 was 45-56%).
// Emissions stream through a 16-slot cp.async ring (15-step lookahead).
// Mask: 1 ballot bit per (seq, step). Renorm: exact pow-2 every 4 steps.
// ---------------------------------------------------------------------------
__global__ __launch_bounds__(96, 1) void crf_fwd_kernel(
    const float* __restrict__ em, const int* __restrict__ mask,
    const float* __restrict__ trans, const float* __restrict__ startt,
    const float* __restrict__ endt)
{
    __shared__ __align__(16) float sh_u[2][96];        // [0..47]=A, [48..95]=B
    __shared__ __align__(16) float sh_em[RING][128];   // ring: [0..47]=A, [64..111]=B
    __shared__ unsigned mb[2][32];                     // mask bits per seq
    __shared__ float sc[96];

    const int tid = threadIdx.x;
    const int seq = tid >= 48;            // 0 = A, 1 = B
    const int j   = tid - seq * 48;
    const int bA  = blockIdx.x * 2;
    const int bme = bA + seq;             // this thread's batch element

    // ---- mask bits via ballot (warp 0 does both sequences) ----
    if (tid < 32) {
        #pragma unroll 1
        for (int k = 0; k < 32; k++) {
            int vA = mask[bA * TT + k * 32 + tid];
            unsigned wA = __ballot_sync(0xFFFFFFFFu, vA != 0);
            if (tid == k) mb[0][k] = wA;
            int vB = mask[(bA + 1) * TT + k * 32 + tid];
            unsigned wB = __ballot_sync(0xFFFFFFFFu, vB != 0);
            if (tid == k) mb[1][k] = wB;
        }
    }

    // ---- transition column j, exponentiated, scalar (48 regs) ----
    float et[L];
    #pragma unroll
    for (int i = 0; i < L; i++)
        et[i] = ex2f(trans[i * L + j] * LOG2E);
    const float expEnd = ex2f(endt[j] * LOG2E);

    // ---- initial state u0 = exp(start + em[0]) ----
    float res = ex2f((startt[j] + em[(size_t)bme * TT * L + j]) * LOG2E);
    sh_u[0][seq * 48 + j] = res;

    // ---- cp.async producer: lanes 0..11 -> seq A, 12..23 -> seq B ----
    const float* gbase = (tid < 12) ? (em + (size_t)bA * TT * L + tid * 4)
                                    : (em + (size_t)(bA + 1) * TT * L + (tid - 12) * 4);
    const unsigned dst_off  = (tid < 12) ? (unsigned)(tid * 16) : (unsigned)(256 + (tid - 12) * 16);
    const unsigned ring_base = smem_u32(&sh_em[0][0]);

    for (int tp = 1; tp < RING; ++tp) {
        if (tid < 24) {
            const float* src = gbase + (size_t)tp * L;
            unsigned d = ring_base + (unsigned)tp * 512u + dst_off;
            asm volatile("cp.async.cg.shared.global [%0], [%1], 16;" :: "r"(d), "l"(src));
        }
        asm volatile("cp.async.commit_group;");
    }
    asm volatile("cp.async.wait_group 14;");   // row 1 resident
    __syncthreads();

    int iA = 0;                                // exact integer log2 credit
    const float* pr = &sh_u[0][seq * 48];
    float*       pw = &sh_u[1][seq * 48];

    #pragma unroll 1
    for (int t = 1; t < TT; ++t) {
        // ---- scalar 48-FMA dot (12 broadcast LDS.128, 4 accumulators) ----
        const float4* up = reinterpret_cast<const float4*>(pr);
        float a0 = 0.f, a1 = 0.f, a2 = 0.f, a3 = 0.f;
        float first = 0.f;
        #pragma unroll
        for (int q = 0; q < 12; q++) {
            float4 v = up[q];
            if (q == 0) first = v.x;           // u[t-1][0] (renorm reference)
            a0 = fmaf(v.x, et[4 * q + 0], a0);
            a1 = fmaf(v.y, et[4 * q + 1], a1);
            a2 = fmaf(v.z, et[4 * q + 2], a2);
            a3 = fmaf(v.w, et[4 * q + 3], a3);
        }
        float dot = (a0 + a1) + (a2 + a3);

        // ---- emission + mask bit ----
        const int slot = t & (RING - 1);
        float Ee = ex2f(sh_em[slot][seq * 64 + j] * LOG2E);
        float prod = dot * Ee;
        bool mbit = (mb[seq][t >> 5] >> (t & 31)) & 1u;
        float sel = mbit ? prod : res;

        if ((t & 3) == 0) {                    // exact power-of-2 renorm
            unsigned eb = __float_as_uint(first) & 0x7F800000u;
            sel *= __uint_as_float(0x7F000000u - eb);
            iA += (int)(eb >> 23) - 127;
        }
        res = sel;
        pw[j] = res;

        // ---- refill ring slot for row t+15 (clamped) ----
        {
            int tf = t + (RING - 1); if (tf > TT - 1) tf = TT - 1;
            if (tid < 24) {
                const float* src = gbase + (size_t)tf * L;
                unsigned d = ring_base + (unsigned)(tf & (RING - 1)) * 512u + dst_off;
                asm volatile("cp.async.cg.shared.global [%0], [%1], 16;" :: "r"(d), "l"(src));
            }
            asm volatile("cp.async.commit_group;");
            asm volatile("cp.async.wait_group 14;");   // row t+1 resident
        }

        float* tmp = (float*)pr; pr = pw; pw = tmp;
        __syncthreads();
    }

    // ---- finalize: logZ = (log2(sum_j u_j * exp(end_j)) + credit) * ln2 ----
    sc[tid] = res * expEnd;
    __syncthreads();
    if (j == 0) {                              // tid 0 (seq A) and tid 48 (seq B)
        float s = 0.f;
        #pragma unroll
        for (int q = 0; q < L; q++) s += sc[seq * 48 + q];
        g_fwd[bme] = (lg2f(s) + (float)iA) * LN2;
    }
}

// ---------------------------------------------------------------------------
// Gold score kernel: one block per batch element.
// ---------------------------------------------------------------------------
__global__ __launch_bounds__(256, 4) void crf_gold_kernel(
    const float* __restrict__ em, const int* __restrict__ labels,
    const int* __restrict__ mask, const float* __restrict__ trans,
    const float* __restrict__ startt, const float* __restrict__ endt)
{
    __shared__ float red[256];
    __shared__ int   redc[256];
    const int b = blockIdx.x;
    const int tid = threadIdx.x;

    float acc = 0.f;
    int cnt = 0;
    for (int t = tid; t < TT; t += 256) {
        int l = labels[b * TT + t];
        int m = mask[b * TT + t];
        cnt += m;
        float e = em[((size_t)(b * TT) + t) * L + l];
        if (t == 0) {
            acc += startt[l] + e;
        } else {
            int lp = labels[b * TT + t - 1];
            acc += (e + trans[l * L + lp]) * (float)m;
        }
    }
    red[tid] = acc; redc[tid] = cnt;
    __syncthreads();
    for (int s = 128; s > 0; s >>= 1) {
        if (tid < s) { red[tid] += red[tid + s]; redc[tid] += redc[tid + s]; }
        __syncthreads();
    }
    if (tid == 0) {
        int len = redc[0] - 1;
        int last = labels[b * TT + len];
        g_gold[b] = red[0] + endt[last];
    }
}

// ---------------------------------------------------------------------------
// Final reduction: mean(fwd - gold)
// ---------------------------------------------------------------------------
__global__ __launch_bounds__(512, 1) void crf_final_kernel(float* __restrict__ out)
{
    __shared__ float red[512];
    int tid = threadIdx.x;
    red[tid] = g_fwd[tid] - g_gold[tid];
    __syncthreads();
    for (int s = 256; s > 0; s >>= 1) {
        if (tid < s) red[tid] += red[tid + s];
        __syncthreads();
    }
    if (tid == 0) out[0] = red[0] * (1.0f / (float)B);
}

extern "C" void kernel_launch(void* const* d_in, const int* in_sizes, int n_in,
                              void* d_out, int out_size)
{
    const float* em     = (const float*)d_in[0];
    const int*   labels = (const int*)  d_in[1];
    const int*   mask   = (const int*)  d_in[2];
    const float* trans  = (const float*)d_in[3];
    const float* startt = (const float*)d_in[4];
    const float* endt   = (const float*)d_in[5];
    float* out = (float*)d_out;

    crf_fwd_kernel<<<B / 2, 96>>>(em, mask, trans, startt, endt);
    crf_gold_kernel<<<B, 256>>>(em, labels, mask, trans, startt, endt);
    crf_final_kernel<<<1, 512>>>(out);
}